// round 3
// baseline (speedup 1.0000x reference)
#include <cuda_runtime.h>
#include <cuda_fp16.h>
#include <cstdint>
#include <math.h>

static constexpr int Nd   = 8192;
static constexpr int Bd   = 256;
static constexpr int NNZc = 16 * Nd;

// ---------------- device scratch (no allocation) ----------------
__device__ __align__(1024) float  g_xt[Nd * Bd];        // x^T [N,B] fp32
__device__ __align__(1024) __half g_a0h[Bd * Nd];       // activations fp16 [B,N]
__device__ __align__(1024) __half g_h1h[Bd * Nd];
__device__ __align__(1024) __half g_h2h[Bd * Nd];
__device__ __align__(1024) __half g_w16[3u * Nd * Nd];  // fp16 weights, 403MB
__device__ int   g_cnt[Nd];
__device__ int   g_rowptr[Nd + 1];
__device__ int   g_cursor[Nd];
__device__ int   g_sc[NNZc];
__device__ float g_sv[NNZc];

// ---------------- helpers ----------------
__device__ __forceinline__ uint32_t smem_to_u32(const void* p) {
    uint32_t a;
    asm("{ .reg .u64 t; cvta.to.shared.u64 t, %1; cvt.u32.u64 %0, t; }" : "=r"(a) : "l"(p));
    return a;
}

__device__ __forceinline__ float selu_f(float x) {
    const float kS = 1.0507009873554805f;
    const float kA = 1.6732632423543772f;
    return x > 0.f ? kS * x : kS * kA * expm1f(x);
}

// SW128 swizzle for a 128-row x 32-half tile stored as 64 x 128B rows
// (logical row r, half-column c) -> byte offset within tile
__device__ __forceinline__ uint32_t swz(uint32_t r, uint32_t c) {
    uint32_t byte = (r >> 1) * 128u + (r & 1u) * 64u + c * 2u;
    return byte ^ ((byte >> 3) & 0x70u);
}

#define CP_ASYNC16(dst, src) \
    asm volatile("cp.async.cg.shared.global [%0], [%1], 16;" :: "r"(dst), "l"(src) : "memory")
#define CP_COMMIT() asm volatile("cp.async.commit_group;" ::: "memory")
#define CP_WAIT3()  asm volatile("cp.async.wait_group 3;" ::: "memory")

#define LDMATRIX_X4(r0, r1, r2, r3, addr) \
    asm volatile("ldmatrix.sync.aligned.m8n8.x4.shared.b16 {%0,%1,%2,%3}, [%4];" \
        : "=r"(r0), "=r"(r1), "=r"(r2), "=r"(r3) : "r"(addr))

#define MMA16816(d, a, b0, b1) \
    asm volatile("mma.sync.aligned.m16n8k16.row.col.f32.f16.f16.f32 " \
        "{%0,%1,%2,%3}, {%4,%5,%6,%7}, {%8,%9}, {%0,%1,%2,%3};" \
        : "+f"((d)[0]), "+f"((d)[1]), "+f"((d)[2]), "+f"((d)[3]) \
        : "r"((a)[0]), "r"((a)[1]), "r"((a)[2]), "r"((a)[3]), "r"(b0), "r"(b1))

// ---------------- sparse pipeline ----------------
__global__ void hist_kernel(const int* __restrict__ rows) {
    for (int i = blockIdx.x * blockDim.x + threadIdx.x; i < NNZc; i += gridDim.x * blockDim.x)
        atomicAdd(&g_cnt[rows[i]], 1);
}

__global__ void scan_kernel() {
    __shared__ int wsum[32];
    int t = threadIdx.x, lane = t & 31, w = t >> 5;
    int v[8], s = 0;
#pragma unroll
    for (int i = 0; i < 8; i++) { v[i] = g_cnt[t * 8 + i]; s += v[i]; }
    int x = s;
#pragma unroll
    for (int o = 1; o < 32; o <<= 1) {
        int y = __shfl_up_sync(0xFFFFFFFFu, x, o);
        if (lane >= o) x += y;
    }
    if (lane == 31) wsum[w] = x;
    __syncthreads();
    if (w == 0) {
        int y = wsum[lane];
#pragma unroll
        for (int o = 1; o < 32; o <<= 1) {
            int z = __shfl_up_sync(0xFFFFFFFFu, y, o);
            if (lane >= o) y += z;
        }
        wsum[lane] = y;
    }
    __syncthreads();
    int run = x - s + (w > 0 ? wsum[w - 1] : 0);
#pragma unroll
    for (int i = 0; i < 8; i++) {
        g_rowptr[t * 8 + i] = run;
        g_cursor[t * 8 + i] = run;
        run += v[i];
    }
    if (t == 1023) g_rowptr[Nd] = run;
}

__global__ void build_kernel(const int* __restrict__ rows, const int* __restrict__ cols,
                             const float* __restrict__ vals) {
    for (int i = blockIdx.x * blockDim.x + threadIdx.x; i < NNZc; i += gridDim.x * blockDim.x) {
        int p = atomicAdd(&g_cursor[rows[i]], 1);
        g_sc[p] = cols[i];
        g_sv[p] = vals[i];
    }
}

__global__ void transpose_kernel(const float* __restrict__ x) {
    __shared__ float t[32][33];
    int nb = blockIdx.x * 32, bb = blockIdx.y * 32;
    int tx = threadIdx.x, ty = threadIdx.y;
#pragma unroll
    for (int i = 0; i < 32; i += 8)
        t[ty + i][tx] = x[(size_t)(bb + ty + i) * Nd + nb + tx];
    __syncthreads();
#pragma unroll
    for (int i = 0; i < 32; i += 8)
        g_xt[(size_t)(nb + ty + i) * Bd + bb + tx] = t[tx][ty + i];
}

__global__ void spmv_kernel(const float* __restrict__ bc, const float* __restrict__ flag) {
    int row = blockIdx.x * 8 + (threadIdx.x >> 5);
    int lane = threadIdx.x & 31;
    int s = g_rowptr[row], e = g_rowptr[row + 1];
    float a0 = 0.f, a1 = 0.f, a2 = 0.f, a3 = 0.f, a4 = 0.f, a5 = 0.f, a6 = 0.f, a7 = 0.f;
    const float* xb = g_xt + lane * 8;
    for (int j = s; j < e; j++) {
        float v = g_sv[j];
        const float4* p = (const float4*)(xb + (size_t)g_sc[j] * Bd);
        float4 u = p[0], w = p[1];
        a0 += v * u.x; a1 += v * u.y; a2 += v * u.z; a3 += v * u.w;
        a4 += v * w.x; a5 += v * w.y; a6 += v * w.z; a7 += v * w.w;
    }
    float bcv = bc[row], fl = flag[row];
    float r[8] = {a0, a1, a2, a3, a4, a5, a6, a7};
#pragma unroll
    for (int i = 0; i < 8; i++)
        g_a0h[(size_t)(lane * 8 + i) * Nd + row] = __float2half_rn(bcv + r[i] * fl);
}

// ---------------- weight fp32 -> fp16 ----------------
__global__ void convertw_kernel(const float* __restrict__ w, __half* __restrict__ o) {
    int i = blockIdx.x * blockDim.x + threadIdx.x;   // handles 8 elements
    const float4* s = (const float4*)w;
    float4 a = s[i * 2], b = s[i * 2 + 1];
    __half2 h0 = __floats2half2_rn(a.x, a.y);
    __half2 h1 = __floats2half2_rn(a.z, a.w);
    __half2 h2 = __floats2half2_rn(b.x, b.y);
    __half2 h3 = __floats2half2_rn(b.z, b.w);
    uint4 pk;
    pk.x = *(uint32_t*)&h0; pk.y = *(uint32_t*)&h1;
    pk.z = *(uint32_t*)&h2; pk.w = *(uint32_t*)&h3;
    ((uint4*)o)[i] = pk;
}

// ---------------- fp16 mma.sync GEMM ----------------
// C[256,8192] = A[256,8192] x W[n,k]^T  (both fp16, K-major), fp32 accum
// grid 128: bx&1 = mtile (128 rows), bx>>1 = ntile (128 cols)
// 8 warps: wm = w&1 (64 rows), wn = w>>2.. -> w>>1 (32 cols). warp tile 64x32.
static constexpr int NSTAGE      = 5;
static constexpr int STAGE_BYTES = 16384;   // 8KB A + 8KB B (128x32 halves each)
static constexpr int GEMM_SMEM   = NSTAGE * STAGE_BYTES;
static constexpr int KTILES      = Nd / 32; // 256

__device__ __forceinline__ void issue_stage(uint32_t sbase, int buf,
                                            const __half* At, const __half* Wt,
                                            int k0, int tid) {
    uint32_t st = sbase + buf * STAGE_BYTES;
#pragma unroll
    for (int i = 0; i < 4; i++) {
        int id   = tid + i * 256;        // 0..1023
        int tile = id >> 9;              // 0=A, 1=B
        int l    = id & 511;
        int r    = l >> 2, c8 = l & 3;
        const __half* src = (tile ? Wt : At) + (size_t)r * Nd + k0 + c8 * 8;
        uint32_t dst = st + tile * 8192 + swz(r, c8 * 8);
        CP_ASYNC16(dst, src);
    }
}

__global__ void __launch_bounds__(256, 1)
gemm_f16_kernel(const __half* __restrict__ Ag, const __half* __restrict__ Wg,
                const float* __restrict__ bias,
                const float* __restrict__ bc, const float* __restrict__ flag,
                void* __restrict__ outv, int mode)   // 0=selu->half, 1=addcmul->float
{
    extern __shared__ char smem[];
    uint32_t sb = smem_to_u32(smem);
    int tid = threadIdx.x, lane = tid & 31, w = tid >> 5;
    int wm = w & 1, wn = w >> 1;
    int mtile = blockIdx.x & 1, ntile = blockIdx.x >> 1;

    const __half* At = Ag + (size_t)(mtile * 128) * Nd;
    const __half* Wt = Wg + (size_t)(ntile * 128) * Nd;

    float acc[4][4][4];
#pragma unroll
    for (int a = 0; a < 4; a++)
#pragma unroll
        for (int b = 0; b < 4; b++)
#pragma unroll
            for (int c = 0; c < 4; c++) acc[a][b][c] = 0.f;

#pragma unroll
    for (int s = 0; s < NSTAGE - 1; s++) {
        issue_stage(sb, s, At, Wt, s * 32, tid);
        CP_COMMIT();
    }

    for (int t = 0; t < KTILES; t++) {
        CP_WAIT3();
        __syncthreads();
        // prefetch next stage into buffer (t-1)%5 — safe after the barrier
        if (t + NSTAGE - 1 < KTILES)
            issue_stage(sb, (t + NSTAGE - 1) % NSTAGE, At, Wt, (t + NSTAGE - 1) * 32, tid);
        CP_COMMIT();

        uint32_t aB = sb + (t % NSTAGE) * STAGE_BYTES;
        uint32_t bB = aB + 8192;
#pragma unroll
        for (int ks = 0; ks < 2; ks++) {
            uint32_t ar[4][4], br[2][4];
            uint32_t col = ks * 16 + (lane >> 4) * 8;
#pragma unroll
            for (int mf = 0; mf < 4; mf++) {
                uint32_t row = wm * 64 + mf * 16 + (lane & 15);
                uint32_t ad = aB + swz(row, col);
                LDMATRIX_X4(ar[mf][0], ar[mf][1], ar[mf][2], ar[mf][3], ad);
            }
#pragma unroll
            for (int p = 0; p < 2; p++) {
                uint32_t row = wn * 32 + p * 16 + (lane & 15);
                uint32_t ad = bB + swz(row, col);
                LDMATRIX_X4(br[p][0], br[p][1], br[p][2], br[p][3], ad);
            }
#pragma unroll
            for (int mf = 0; mf < 4; mf++)
#pragma unroll
                for (int nf = 0; nf < 4; nf++) {
                    uint32_t b0 = br[nf >> 1][nf & 1];
                    uint32_t b1 = br[nf >> 1][2 + (nf & 1)];
                    MMA16816(acc[mf][nf], ar[mf], b0, b1);
                }
        }
    }

    // epilogue: c0/c1 at (row=lane>>2, col=2*(lane&3)), c2/c3 at row+8
#pragma unroll
    for (int mf = 0; mf < 4; mf++) {
#pragma unroll
        for (int nf = 0; nf < 4; nf++) {
            int r0 = mtile * 128 + wm * 64 + mf * 16 + (lane >> 2);
            int c0 = ntile * 128 + wn * 32 + nf * 8 + (lane & 3) * 2;
            float b0 = __ldg(&bias[c0]), b1 = __ldg(&bias[c0 + 1]);
            float v00 = acc[mf][nf][0] + b0, v01 = acc[mf][nf][1] + b1;
            float v10 = acc[mf][nf][2] + b0, v11 = acc[mf][nf][3] + b1;
            if (mode == 0) {
                __half2* o0 = (__half2*)((__half*)outv + (size_t)r0 * Nd + c0);
                __half2* o1 = (__half2*)((__half*)outv + (size_t)(r0 + 8) * Nd + c0);
                *o0 = __floats2half2_rn(selu_f(v00), selu_f(v01));
                *o1 = __floats2half2_rn(selu_f(v10), selu_f(v11));
            } else {
                float bc0 = __ldg(&bc[c0]), bc1 = __ldg(&bc[c0 + 1]);
                float fl0 = __ldg(&flag[c0]), fl1 = __ldg(&flag[c0 + 1]);
                float* o0 = (float*)outv + (size_t)r0 * Nd + c0;
                float* o1 = (float*)outv + (size_t)(r0 + 8) * Nd + c0;
                o0[0] = bc0 + v00 * fl0; o0[1] = bc1 + v01 * fl1;
                o1[0] = bc0 + v10 * fl0; o1[1] = bc1 + v11 * fl1;
            }
        }
    }
}

// ---------------- host ----------------
extern "C" void kernel_launch(void* const* d_in, const int* in_sizes, int n_in,
                              void* d_out, int out_size) {
    const float* x    = (const float*)d_in[0];
    const float* vals = (const float*)d_in[1];
    const float* bc   = (const float*)d_in[2];
    const float* flag = (const float*)d_in[3];
    const float* W1   = (const float*)d_in[4];
    const float* b1   = (const float*)d_in[5];
    const float* W2   = (const float*)d_in[6];
    const float* b2   = (const float*)d_in[7];
    const float* W3   = (const float*)d_in[8];
    const float* b3   = (const float*)d_in[9];
    const int*   rows = (const int*)d_in[10];
    const int*   cols = (const int*)d_in[11];

    void *pw16, *pa0, *ph1, *ph2, *pcnt;
    cudaGetSymbolAddress(&pw16, g_w16);
    cudaGetSymbolAddress(&pa0, g_a0h);
    cudaGetSymbolAddress(&ph1, g_h1h);
    cudaGetSymbolAddress(&ph2, g_h2h);
    cudaGetSymbolAddress(&pcnt, g_cnt);

    __half* w16a = (__half*)pw16;
    __half* w16b = w16a + (size_t)Nd * Nd;
    __half* w16c = w16b + (size_t)Nd * Nd;

    cudaFuncSetAttribute(gemm_f16_kernel, cudaFuncAttributeMaxDynamicSharedMemorySize, GEMM_SMEM);

    const int cwBlocks = (Nd * Nd / 8) / 256;   // 32768
    convertw_kernel<<<cwBlocks, 256>>>(W1, w16a);
    convertw_kernel<<<cwBlocks, 256>>>(W2, w16b);
    convertw_kernel<<<cwBlocks, 256>>>(W3, w16c);

    cudaMemsetAsync(pcnt, 0, Nd * sizeof(int));
    hist_kernel<<<256, 256>>>(rows);
    scan_kernel<<<1, 1024>>>();
    build_kernel<<<256, 256>>>(rows, cols, vals);
    transpose_kernel<<<dim3(Nd / 32, Bd / 32), dim3(32, 8)>>>(x);
    spmv_kernel<<<Nd / 8, 256>>>(bc, flag);

    gemm_f16_kernel<<<128, 256, GEMM_SMEM>>>((__half*)pa0, w16a, b1, bc, flag, ph1, 0);
    gemm_f16_kernel<<<128, 256, GEMM_SMEM>>>((__half*)ph1, w16b, b2, bc, flag, ph2, 0);
    gemm_f16_kernel<<<128, 256, GEMM_SMEM>>>((__half*)ph2, w16c, b3, bc, flag, d_out, 1);
}

// round 4
// speedup vs baseline: 1.0840x; 1.0840x over previous
#include <cuda_runtime.h>
#include <cuda_fp16.h>
#include <cstdint>
#include <math.h>

static constexpr int Nd   = 8192;
static constexpr int Bd   = 256;
static constexpr int NNZc = 16 * Nd;

// ---------------- device scratch (no allocation) ----------------
__device__ __align__(1024) float  g_xt[Nd * Bd];        // x^T [N,B] fp32
__device__ __align__(1024) __half g_a0h[Bd * Nd];       // activations fp16 [B,N]
__device__ __align__(1024) __half g_h1h[Bd * Nd];
__device__ __align__(1024) __half g_h2h[Bd * Nd];
__device__ int   g_rowptr[Nd + 1];
__device__ int   g_cursor[Nd];
__device__ int   g_sc[NNZc];
__device__ float g_sv[NNZc];

// ---------------- helpers ----------------
__device__ __forceinline__ uint32_t smem_to_u32(const void* p) {
    uint32_t a;
    asm("{ .reg .u64 t; cvta.to.shared.u64 t, %1; cvt.u32.u64 %0, t; }" : "=r"(a) : "l"(p));
    return a;
}

__device__ __forceinline__ float selu_f(float x) {
    const float kS = 1.0507009873554805f;
    const float kA = 1.6732632423543772f;
    return x > 0.f ? kS * x : kS * kA * expm1f(x);
}

// SW128 swizzle, A tile: 128 rows x 32 halves packed as 64 x 128B rows
__device__ __forceinline__ uint32_t swzA(uint32_t r, uint32_t c) {
    uint32_t byte = (r >> 1) * 128u + (r & 1u) * 64u + c * 2u;
    return byte ^ ((byte >> 3) & 0x70u);
}
// SW128 swizzle, B tile: 128 rows x 32 fp32 = 128 x 128B rows
__device__ __forceinline__ uint32_t swzB(uint32_t r, uint32_t cw) {
    uint32_t byte = r * 128u + cw * 4u;
    return byte ^ ((byte >> 3) & 0x70u);
}

#define CP_ASYNC16(dst, src) \
    asm volatile("cp.async.cg.shared.global [%0], [%1], 16;" :: "r"(dst), "l"(src) : "memory")
#define CP_COMMIT() asm volatile("cp.async.commit_group;" ::: "memory")
#define CP_WAIT3()  asm volatile("cp.async.wait_group 3;" ::: "memory")

#define LDMATRIX_X4(r0, r1, r2, r3, addr) \
    asm volatile("ldmatrix.sync.aligned.m8n8.x4.shared.b16 {%0,%1,%2,%3}, [%4];" \
        : "=r"(r0), "=r"(r1), "=r"(r2), "=r"(r3) : "r"(addr))

#define MMA16816(d, a, b0, b1) \
    asm volatile("mma.sync.aligned.m16n8k16.row.col.f32.f16.f16.f32 " \
        "{%0,%1,%2,%3}, {%4,%5,%6,%7}, {%8,%9}, {%0,%1,%2,%3};" \
        : "+f"((d)[0]), "+f"((d)[1]), "+f"((d)[2]), "+f"((d)[3]) \
        : "r"((a)[0]), "r"((a)[1]), "r"((a)[2]), "r"((a)[3]), "r"(b0), "r"(b1))

// ---------------- sparse pipeline ----------------
// fused zero + histogram + scan, single CTA (keeps GEMM2 at ncu launch index 5)
__global__ void __launch_bounds__(1024, 1) histscan_kernel(const int* __restrict__ rows) {
    __shared__ int cnt[Nd];
    __shared__ int wsum[32];
    int t = threadIdx.x, lane = t & 31, w = t >> 5;
#pragma unroll
    for (int i = 0; i < Nd / 1024; i++) cnt[t + i * 1024] = 0;
    __syncthreads();
    const int4* r4 = (const int4*)rows;
    for (int i = t; i < NNZc / 4; i += 1024) {
        int4 v = r4[i];
        atomicAdd(&cnt[v.x], 1); atomicAdd(&cnt[v.y], 1);
        atomicAdd(&cnt[v.z], 1); atomicAdd(&cnt[v.w], 1);
    }
    __syncthreads();
    int v[8], s = 0;
#pragma unroll
    for (int i = 0; i < 8; i++) { v[i] = cnt[t * 8 + i]; s += v[i]; }
    int x = s;
#pragma unroll
    for (int o = 1; o < 32; o <<= 1) {
        int y = __shfl_up_sync(0xFFFFFFFFu, x, o);
        if (lane >= o) x += y;
    }
    if (lane == 31) wsum[w] = x;
    __syncthreads();
    if (w == 0) {
        int y = wsum[lane];
#pragma unroll
        for (int o = 1; o < 32; o <<= 1) {
            int z = __shfl_up_sync(0xFFFFFFFFu, y, o);
            if (lane >= o) y += z;
        }
        wsum[lane] = y;
    }
    __syncthreads();
    int run = x - s + (w > 0 ? wsum[w - 1] : 0);
#pragma unroll
    for (int i = 0; i < 8; i++) {
        g_rowptr[t * 8 + i] = run;
        g_cursor[t * 8 + i] = run;
        run += v[i];
    }
    if (t == 1023) g_rowptr[Nd] = run;
}

__global__ void build_kernel(const int* __restrict__ rows, const int* __restrict__ cols,
                             const float* __restrict__ vals) {
    for (int i = blockIdx.x * blockDim.x + threadIdx.x; i < NNZc; i += gridDim.x * blockDim.x) {
        int p = atomicAdd(&g_cursor[rows[i]], 1);
        g_sc[p] = cols[i];
        g_sv[p] = vals[i];
    }
}

__global__ void transpose_kernel(const float* __restrict__ x) {
    __shared__ float t[32][33];
    int nb = blockIdx.x * 32, bb = blockIdx.y * 32;
    int tx = threadIdx.x, ty = threadIdx.y;
#pragma unroll
    for (int i = 0; i < 32; i += 8)
        t[ty + i][tx] = x[(size_t)(bb + ty + i) * Nd + nb + tx];
    __syncthreads();
#pragma unroll
    for (int i = 0; i < 32; i += 8)
        g_xt[(size_t)(nb + ty + i) * Bd + bb + tx] = t[tx][ty + i];
}

__global__ void spmv_kernel(const float* __restrict__ bc, const float* __restrict__ flag) {
    int row = blockIdx.x * 8 + (threadIdx.x >> 5);
    int lane = threadIdx.x & 31;
    int s = g_rowptr[row], e = g_rowptr[row + 1];
    float a0 = 0.f, a1 = 0.f, a2 = 0.f, a3 = 0.f, a4 = 0.f, a5 = 0.f, a6 = 0.f, a7 = 0.f;
    const float* xb = g_xt + lane * 8;
    for (int j = s; j < e; j++) {
        float v = g_sv[j];
        const float4* p = (const float4*)(xb + (size_t)g_sc[j] * Bd);
        float4 u = p[0], w = p[1];
        a0 += v * u.x; a1 += v * u.y; a2 += v * u.z; a3 += v * u.w;
        a4 += v * w.x; a5 += v * w.y; a6 += v * w.z; a7 += v * w.w;
    }
    float bcv = bc[row], fl = flag[row];
    float r[8] = {a0, a1, a2, a3, a4, a5, a6, a7};
#pragma unroll
    for (int i = 0; i < 8; i++)
        g_a0h[(size_t)(lane * 8 + i) * Nd + row] = __float2half_rn(bcv + r[i] * fl);
}

// ---------------- fp16 mma.sync GEMM, fp32 weights converted in-register ----------------
// C[256,8192] = A[256,8192](fp16) x W[n,k](fp32)^T, fp32 accum
// grid 128: bx&1 = mtile (128 rows), bx>>1 = ntile (128 cols); 8 warps, warp tile 64x32
static constexpr int NSTAGE      = 5;
static constexpr int A_BYTES     = 8192;    // 128x32 halves
static constexpr int B_BYTES     = 16384;   // 128x32 fp32
static constexpr int STAGE_BYTES = A_BYTES + B_BYTES;
static constexpr int GEMM_SMEM   = NSTAGE * STAGE_BYTES;   // 120 KB
static constexpr int KTILES      = Nd / 32; // 256

__device__ __forceinline__ void issue_stage(uint32_t sbase, int buf,
                                            const __half* At, const float* Wt,
                                            int k0, int tid) {
    uint32_t st = sbase + buf * STAGE_BYTES;
    // A: 512 x 16B chunks (row = 64B = 4 chunks)
#pragma unroll
    for (int i = 0; i < 2; i++) {
        int id = tid + i * 256;
        int r = id >> 2, c16 = id & 3;
        const __half* src = At + (size_t)r * Nd + k0 + c16 * 8;
        CP_ASYNC16(st + swzA(r, c16 * 8), src);
    }
    // B: 1024 x 16B chunks (row = 128B = 8 chunks), fp32
#pragma unroll
    for (int i = 0; i < 4; i++) {
        int id = tid + i * 256;
        int r = id >> 3, ch = id & 7;
        const float* src = Wt + (size_t)r * Nd + k0 + ch * 4;
        CP_ASYNC16(st + A_BYTES + swzB(r, ch * 4), src);
    }
}

__global__ void __launch_bounds__(256, 1)
gemm_f16_kernel(const __half* __restrict__ Ag, const float* __restrict__ Wg,
                const float* __restrict__ bias,
                const float* __restrict__ bc, const float* __restrict__ flag,
                void* __restrict__ outv, int mode)   // 0=selu->half, 1=addcmul->float
{
    extern __shared__ char smem[];
    uint32_t sb = smem_to_u32(smem);
    int tid = threadIdx.x, lane = tid & 31, w = tid >> 5;
    int wm = w & 1, wn = w >> 1;
    int mtile = blockIdx.x & 1, ntile = blockIdx.x >> 1;

    const __half* At = Ag + (size_t)(mtile * 128) * Nd;
    const float*  Wt = Wg + (size_t)(ntile * 128) * Nd;

    float acc[4][4][4];
#pragma unroll
    for (int a = 0; a < 4; a++)
#pragma unroll
        for (int b = 0; b < 4; b++)
#pragma unroll
            for (int c = 0; c < 4; c++) acc[a][b][c] = 0.f;

#pragma unroll
    for (int s = 0; s < NSTAGE - 1; s++) {
        issue_stage(sb, s, At, Wt, s * 32, tid);
        CP_COMMIT();
    }

    for (int t = 0; t < KTILES; t++) {
        CP_WAIT3();
        __syncthreads();
        if (t + NSTAGE - 1 < KTILES)
            issue_stage(sb, (t + NSTAGE - 1) % NSTAGE, At, Wt, (t + NSTAGE - 1) * 32, tid);
        CP_COMMIT();

        uint32_t aB = sb + (t % NSTAGE) * STAGE_BYTES;
        uint32_t bB = aB + A_BYTES;
#pragma unroll
        for (int ks = 0; ks < 2; ks++) {
            uint32_t ar[4][4];
            uint32_t acol = ks * 16 + (lane >> 4) * 8;
#pragma unroll
            for (int mf = 0; mf < 4; mf++) {
                uint32_t row = wm * 64 + mf * 16 + (lane & 15);
                LDMATRIX_X4(ar[mf][0], ar[mf][1], ar[mf][2], ar[mf][3], aB + swzA(row, acol));
            }
            // B fragments: lds.64 fp32 pair -> cvt half2, per nf
            uint32_t b0r[4], b1r[4];
            uint32_t nrow = wn * 32 + (lane >> 2);
            uint32_t clo = ks * 16 + (lane & 3) * 2;
#pragma unroll
            for (int nf = 0; nf < 4; nf++) {
                uint32_t r = nrow + nf * 8;
                float2 lo = *(const float2*)(smem + (bB - sb) + swzB(r, clo));
                float2 hi = *(const float2*)(smem + (bB - sb) + swzB(r, clo + 8));
                __half2 h0 = __floats2half2_rn(lo.x, lo.y);
                __half2 h1 = __floats2half2_rn(hi.x, hi.y);
                b0r[nf] = *(uint32_t*)&h0;
                b1r[nf] = *(uint32_t*)&h1;
            }
#pragma unroll
            for (int mf = 0; mf < 4; mf++)
#pragma unroll
                for (int nf = 0; nf < 4; nf++)
                    MMA16816(acc[mf][nf], ar[mf], b0r[nf], b1r[nf]);
        }
    }

#pragma unroll
    for (int mf = 0; mf < 4; mf++) {
#pragma unroll
        for (int nf = 0; nf < 4; nf++) {
            int r0 = mtile * 128 + wm * 64 + mf * 16 + (lane >> 2);
            int c0 = ntile * 128 + wn * 32 + nf * 8 + (lane & 3) * 2;
            float b0 = __ldg(&bias[c0]), b1 = __ldg(&bias[c0 + 1]);
            float v00 = acc[mf][nf][0] + b0, v01 = acc[mf][nf][1] + b1;
            float v10 = acc[mf][nf][2] + b0, v11 = acc[mf][nf][3] + b1;
            if (mode == 0) {
                __half2* o0 = (__half2*)((__half*)outv + (size_t)r0 * Nd + c0);
                __half2* o1 = (__half2*)((__half*)outv + (size_t)(r0 + 8) * Nd + c0);
                *o0 = __floats2half2_rn(selu_f(v00), selu_f(v01));
                *o1 = __floats2half2_rn(selu_f(v10), selu_f(v11));
            } else {
                float bc0 = __ldg(&bc[c0]), bc1 = __ldg(&bc[c0 + 1]);
                float fl0 = __ldg(&flag[c0]), fl1 = __ldg(&flag[c0 + 1]);
                float* o0 = (float*)outv + (size_t)r0 * Nd + c0;
                float* o1 = (float*)outv + (size_t)(r0 + 8) * Nd + c0;
                o0[0] = bc0 + v00 * fl0; o0[1] = bc1 + v01 * fl1;
                o1[0] = bc0 + v10 * fl0; o1[1] = bc1 + v11 * fl1;
            }
        }
    }
}

// ---------------- host ----------------
extern "C" void kernel_launch(void* const* d_in, const int* in_sizes, int n_in,
                              void* d_out, int out_size) {
    const float* x    = (const float*)d_in[0];
    const float* vals = (const float*)d_in[1];
    const float* bc   = (const float*)d_in[2];
    const float* flag = (const float*)d_in[3];
    const float* W1   = (const float*)d_in[4];
    const float* b1   = (const float*)d_in[5];
    const float* W2   = (const float*)d_in[6];
    const float* b2   = (const float*)d_in[7];
    const float* W3   = (const float*)d_in[8];
    const float* b3   = (const float*)d_in[9];
    const int*   rows = (const int*)d_in[10];
    const int*   cols = (const int*)d_in[11];

    void *pa0, *ph1, *ph2;
    cudaGetSymbolAddress(&pa0, g_a0h);
    cudaGetSymbolAddress(&ph1, g_h1h);
    cudaGetSymbolAddress(&ph2, g_h2h);

    cudaFuncSetAttribute(gemm_f16_kernel, cudaFuncAttributeMaxDynamicSharedMemorySize, GEMM_SMEM);

    // launch order chosen so ncu (-s 5 -c 1) captures gemm #2 (steady state)
    histscan_kernel<<<1, 1024>>>(rows);                                   // 0
    build_kernel<<<256, 256>>>(rows, cols, vals);                         // 1
    transpose_kernel<<<dim3(Nd / 32, Bd / 32), dim3(32, 8)>>>(x);         // 2
    spmv_kernel<<<Nd / 8, 256>>>(bc, flag);                               // 3
    gemm_f16_kernel<<<128, 256, GEMM_SMEM>>>((__half*)pa0, W1, b1, bc, flag, ph1, 0);   // 4
    gemm_f16_kernel<<<128, 256, GEMM_SMEM>>>((__half*)ph1, W2, b2, bc, flag, ph2, 0);   // 5 <- ncu
    gemm_f16_kernel<<<128, 256, GEMM_SMEM>>>((__half*)ph2, W3, b3, bc, flag, d_out, 1); // 6
}

// round 6
// speedup vs baseline: 1.4355x; 1.3242x over previous
#include <cuda_runtime.h>
#include <cuda_fp16.h>
#include <cstdint>
#include <math.h>

static constexpr int Nd   = 8192;
static constexpr int Bd   = 256;
static constexpr int NNZc = 16 * Nd;

// ---------------- device scratch (no allocation) ----------------
__device__ __align__(1024) float  g_xt[Nd * Bd];        // x^T [N,B] fp32
__device__ __align__(1024) __half g_a0h[Bd * Nd];       // activations fp16 [B,N]
__device__ __align__(1024) __half g_h1h[Bd * Nd];
__device__ __align__(1024) __half g_h2h[Bd * Nd];
__device__ int   g_rowptr[Nd + 1];
__device__ int   g_cursor[Nd];
__device__ int2  g_cv[NNZc];    // packed {col, val-bits}

// ---------------- helpers ----------------
__device__ __forceinline__ uint32_t smem_to_u32(const void* p) {
    uint32_t a;
    asm("{ .reg .u64 t; cvta.to.shared.u64 t, %1; cvt.u32.u64 %0, t; }" : "=r"(a) : "l"(p));
    return a;
}

__device__ __forceinline__ float selu_f(float x) {
    const float kS = 1.0507009873554805f;
    const float kA = 1.6732632423543772f;
    return x > 0.f ? kS * x : kS * kA * expm1f(x);
}

// SW128 swizzle, A tile: 128 rows x 32 halves packed as 64 x 128B rows
__device__ __forceinline__ uint32_t swzA(uint32_t r, uint32_t c) {
    uint32_t byte = (r >> 1) * 128u + (r & 1u) * 64u + c * 2u;
    return byte ^ ((byte >> 3) & 0x70u);
}
// SW128 swizzle, B tile: 128 rows x 32 fp32 = 128 x 128B rows
__device__ __forceinline__ uint32_t swzB(uint32_t r, uint32_t cw) {
    uint32_t byte = r * 128u + cw * 4u;
    return byte ^ ((byte >> 3) & 0x70u);
}

#define CP_ASYNC16(dst, src) \
    asm volatile("cp.async.cg.shared.global [%0], [%1], 16;" :: "r"(dst), "l"(src) : "memory")
#define CP_COMMIT() asm volatile("cp.async.commit_group;" ::: "memory")
#define CP_WAIT2()  asm volatile("cp.async.wait_group 2;" ::: "memory")

#define LDMATRIX_X4(r0, r1, r2, r3, addr) \
    asm volatile("ldmatrix.sync.aligned.m8n8.x4.shared.b16 {%0,%1,%2,%3}, [%4];" \
        : "=r"(r0), "=r"(r1), "=r"(r2), "=r"(r3) : "r"(addr))

#define MMA16816(d, a, b0, b1) \
    asm volatile("mma.sync.aligned.m16n8k16.row.col.f32.f16.f16.f32 " \
        "{%0,%1,%2,%3}, {%4,%5,%6,%7}, {%8,%9}, {%0,%1,%2,%3};" \
        : "+f"((d)[0]), "+f"((d)[1]), "+f"((d)[2]), "+f"((d)[3]) \
        : "r"((a)[0]), "r"((a)[1]), "r"((a)[2]), "r"((a)[3]), "r"(b0), "r"(b1))

// ---------------- sparse pipeline ----------------
__global__ void __launch_bounds__(1024, 1) histscan_kernel(const int* __restrict__ rows) {
    __shared__ int cnt[Nd];
    __shared__ int wsum[32];
    int t = threadIdx.x, lane = t & 31, w = t >> 5;
#pragma unroll
    for (int i = 0; i < Nd / 1024; i++) cnt[t + i * 1024] = 0;
    __syncthreads();
    const int4* r4 = (const int4*)rows;
    for (int i = t; i < NNZc / 4; i += 1024) {
        int4 v = r4[i];
        atomicAdd(&cnt[v.x], 1); atomicAdd(&cnt[v.y], 1);
        atomicAdd(&cnt[v.z], 1); atomicAdd(&cnt[v.w], 1);
    }
    __syncthreads();
    int v[8], s = 0;
#pragma unroll
    for (int i = 0; i < 8; i++) { v[i] = cnt[t * 8 + i]; s += v[i]; }
    int x = s;
#pragma unroll
    for (int o = 1; o < 32; o <<= 1) {
        int y = __shfl_up_sync(0xFFFFFFFFu, x, o);
        if (lane >= o) x += y;
    }
    if (lane == 31) wsum[w] = x;
    __syncthreads();
    if (w == 0) {
        int y = wsum[lane];
#pragma unroll
        for (int o = 1; o < 32; o <<= 1) {
            int z = __shfl_up_sync(0xFFFFFFFFu, y, o);
            if (lane >= o) y += z;
        }
        wsum[lane] = y;
    }
    __syncthreads();
    int run = x - s + (w > 0 ? wsum[w - 1] : 0);
#pragma unroll
    for (int i = 0; i < 8; i++) {
        g_rowptr[t * 8 + i] = run;
        g_cursor[t * 8 + i] = run;
        run += v[i];
    }
    if (t == 1023) g_rowptr[Nd] = run;
}

__global__ void build_kernel(const int* __restrict__ rows, const int* __restrict__ cols,
                             const float* __restrict__ vals) {
    for (int i = blockIdx.x * blockDim.x + threadIdx.x; i < NNZc; i += gridDim.x * blockDim.x) {
        int p = atomicAdd(&g_cursor[rows[i]], 1);
        g_cv[p] = make_int2(cols[i], __float_as_int(vals[i]));
    }
}

__global__ void transpose_kernel(const float* __restrict__ x) {
    __shared__ float t[32][33];
    int nb = blockIdx.x * 32, bb = blockIdx.y * 32;
    int tx = threadIdx.x, ty = threadIdx.y;
#pragma unroll
    for (int i = 0; i < 32; i += 8)
        t[ty + i][tx] = x[(size_t)(bb + ty + i) * Nd + nb + tx];
    __syncthreads();
#pragma unroll
    for (int i = 0; i < 32; i += 8)
        g_xt[(size_t)(nb + ty + i) * Bd + bb + tx] = t[tx][ty + i];
}

__global__ void spmv_kernel(const float* __restrict__ bc, const float* __restrict__ flag) {
    int row = blockIdx.x * 8 + (threadIdx.x >> 5);
    int lane = threadIdx.x & 31;
    int s = g_rowptr[row], e = g_rowptr[row + 1];
    float a0 = 0.f, a1 = 0.f, a2 = 0.f, a3 = 0.f, a4 = 0.f, a5 = 0.f, a6 = 0.f, a7 = 0.f;
    const float* xb = g_xt + lane * 8;
    for (int j = s; j < e; j++) {
        int2 cv = g_cv[j];
        float v = __int_as_float(cv.y);
        const float4* p = (const float4*)(xb + (size_t)cv.x * Bd);
        float4 u = p[0], w = p[1];
        a0 += v * u.x; a1 += v * u.y; a2 += v * u.z; a3 += v * u.w;
        a4 += v * w.x; a5 += v * w.y; a6 += v * w.z; a7 += v * w.w;
    }
    float bcv = bc[row], fl = flag[row];
    float r[8] = {a0, a1, a2, a3, a4, a5, a6, a7};
#pragma unroll
    for (int i = 0; i < 8; i++)
        g_a0h[(size_t)(lane * 8 + i) * Nd + row] = __float2half_rn(bcv + r[i] * fl);
}

// ---------------- fp16 mma.sync GEMM, fp32 weights converted in-register ----------------
static constexpr int NSTAGE      = 5;
static constexpr int A_BYTES     = 8192;    // 128x32 halves
static constexpr int B_BYTES     = 16384;   // 128x32 fp32
static constexpr int STAGE_BYTES = A_BYTES + B_BYTES;
static constexpr int GEMM_SMEM   = NSTAGE * STAGE_BYTES;   // 120 KB
static constexpr int KTILES      = Nd / 32; // 256

__device__ __forceinline__ void issue_stage(uint32_t sbase, int buf,
                                            const __half* At, const float* Wt,
                                            int k0, int tid) {
    uint32_t st = sbase + buf * STAGE_BYTES;
#pragma unroll
    for (int i = 0; i < 2; i++) {
        int id = tid + i * 256;
        int r = id >> 2, c16 = id & 3;
        const __half* src = At + (size_t)r * Nd + k0 + c16 * 8;
        CP_ASYNC16(st + swzA(r, c16 * 8), src);
    }
#pragma unroll
    for (int i = 0; i < 4; i++) {
        int id = tid + i * 256;
        int r = id >> 3, ch = id & 7;
        const float* src = Wt + (size_t)r * Nd + k0 + ch * 4;
        CP_ASYNC16(st + A_BYTES + swzB(r, ch * 4), src);
    }
}

struct Frags {
    uint32_t ar[4][4];
    uint32_t b0r[4], b1r[4];
};

__device__ __forceinline__ void load_frags(Frags& f, const char* smem, uint32_t sb,
                                           int stage, int ks, int wm, int wn, int lane) {
    uint32_t aB = sb + stage * STAGE_BYTES;
    uint32_t bOff = stage * STAGE_BYTES + A_BYTES;
    uint32_t acol = ks * 16 + (lane >> 4) * 8;
#pragma unroll
    for (int mf = 0; mf < 4; mf++) {
        uint32_t row = wm * 64 + mf * 16 + (lane & 15);
        LDMATRIX_X4(f.ar[mf][0], f.ar[mf][1], f.ar[mf][2], f.ar[mf][3], aB + swzA(row, acol));
    }
    uint32_t nrow = wn * 32 + (lane >> 2);
    uint32_t clo = ks * 16 + (lane & 3) * 2;
#pragma unroll
    for (int nf = 0; nf < 4; nf++) {
        uint32_t r = nrow + nf * 8;
        float2 lo = *(const float2*)(smem + bOff + swzB(r, clo));
        float2 hi = *(const float2*)(smem + bOff + swzB(r, clo + 8));
        __half2 h0 = __floats2half2_rn(lo.x, lo.y);
        __half2 h1 = __floats2half2_rn(hi.x, hi.y);
        f.b0r[nf] = *(uint32_t*)&h0;
        f.b1r[nf] = *(uint32_t*)&h1;
    }
}

__global__ void __launch_bounds__(256, 1)
gemm_f16_kernel(const __half* __restrict__ Ag, const float* __restrict__ Wg,
                const float* __restrict__ bias,
                const float* __restrict__ bc, const float* __restrict__ flag,
                void* __restrict__ outv, int mode)   // 0=selu->half, 1=addcmul->float
{
    extern __shared__ char smem[];
    uint32_t sb = smem_to_u32(smem);
    int tid = threadIdx.x, lane = tid & 31, w = tid >> 5;
    int wm = w & 1, wn = w >> 1;
    int mtile = blockIdx.x & 1, ntile = blockIdx.x >> 1;

    const __half* At = Ag + (size_t)(mtile * 128) * Nd;
    const float*  Wt = Wg + (size_t)(ntile * 128) * Nd;

    float acc[4][4][4];
#pragma unroll
    for (int a = 0; a < 4; a++)
#pragma unroll
        for (int b = 0; b < 4; b++)
#pragma unroll
            for (int c = 0; c < 4; c++) acc[a][b][c] = 0.f;

#pragma unroll
    for (int s = 0; s < 4; s++) {
        issue_stage(sb, s, At, Wt, s * 32, tid);
        CP_COMMIT();
    }
    CP_WAIT2();          // groups 0,1 done -> stage 0 ready
    __syncthreads();

    // fixed fragment roles: f0 = (t, ks=0), f1 = (t, ks=1)
    Frags f0, f1;
    load_frags(f0, smem, sb, 0, 0, wm, wn, lane);

#pragma unroll 1
    for (int t = 0; t < KTILES; t++) {
        int st = t % NSTAGE;

        // load (t,1) while issuing MMA(t,0)
        load_frags(f1, smem, sb, st, 1, wm, wn, lane);
#pragma unroll
        for (int mf = 0; mf < 4; mf++)
#pragma unroll
            for (int nf = 0; nf < 4; nf++)
                MMA16816(acc[mf][nf], f0.ar[mf], f0.b0r[nf], f0.b1r[nf]);

        CP_WAIT2();      // stage t+1 guaranteed landed
        __syncthreads(); // stage (t-1)%5 fully consumed by all warps
        if (t + 4 < KTILES)
            issue_stage(sb, (t + 4) % NSTAGE, At, Wt, (t + 4) * 32, tid);
        CP_COMMIT();     // unconditional: keeps group accounting exact

        // load (t+1,0) while issuing MMA(t,1)
        if (t + 1 < KTILES)
            load_frags(f0, smem, sb, (t + 1) % NSTAGE, 0, wm, wn, lane);
#pragma unroll
        for (int mf = 0; mf < 4; mf++)
#pragma unroll
            for (int nf = 0; nf < 4; nf++)
                MMA16816(acc[mf][nf], f1.ar[mf], f1.b0r[nf], f1.b1r[nf]);
    }

#pragma unroll
    for (int mf = 0; mf < 4; mf++) {
#pragma unroll
        for (int nf = 0; nf < 4; nf++) {
            int r0 = mtile * 128 + wm * 64 + mf * 16 + (lane >> 2);
            int c0 = ntile * 128 + wn * 32 + nf * 8 + (lane & 3) * 2;
            float b0 = __ldg(&bias[c0]), b1 = __ldg(&bias[c0 + 1]);
            float v00 = acc[mf][nf][0] + b0, v01 = acc[mf][nf][1] + b1;
            float v10 = acc[mf][nf][2] + b0, v11 = acc[mf][nf][3] + b1;
            if (mode == 0) {
                __half2* o0 = (__half2*)((__half*)outv + (size_t)r0 * Nd + c0);
                __half2* o1 = (__half2*)((__half*)outv + (size_t)(r0 + 8) * Nd + c0);
                *o0 = __floats2half2_rn(selu_f(v00), selu_f(v01));
                *o1 = __floats2half2_rn(selu_f(v10), selu_f(v11));
            } else {
                float bc0 = __ldg(&bc[c0]), bc1 = __ldg(&bc[c0 + 1]);
                float fl0 = __ldg(&flag[c0]), fl1 = __ldg(&flag[c0 + 1]);
                float* o0 = (float*)outv + (size_t)r0 * Nd + c0;
                float* o1 = (float*)outv + (size_t)(r0 + 8) * Nd + c0;
                o0[0] = bc0 + v00 * fl0; o0[1] = bc1 + v01 * fl1;
                o1[0] = bc0 + v10 * fl0; o1[1] = bc1 + v11 * fl1;
            }
        }
    }
}

// ---------------- host ----------------
extern "C" void kernel_launch(void* const* d_in, const int* in_sizes, int n_in,
                              void* d_out, int out_size) {
    const float* x    = (const float*)d_in[0];
    const float* vals = (const float*)d_in[1];
    const float* bc   = (const float*)d_in[2];
    const float* flag = (const float*)d_in[3];
    const float* W1   = (const float*)d_in[4];
    const float* b1   = (const float*)d_in[5];
    const float* W2   = (const float*)d_in[6];
    const float* b2   = (const float*)d_in[7];
    const float* W3   = (const float*)d_in[8];
    const float* b3   = (const float*)d_in[9];
    const int*   rows = (const int*)d_in[10];
    const int*   cols = (const int*)d_in[11];

    void *pa0, *ph1, *ph2;
    cudaGetSymbolAddress(&pa0, g_a0h);
    cudaGetSymbolAddress(&ph1, g_h1h);
    cudaGetSymbolAddress(&ph2, g_h2h);

    cudaFuncSetAttribute(gemm_f16_kernel, cudaFuncAttributeMaxDynamicSharedMemorySize, GEMM_SMEM);

    histscan_kernel<<<1, 1024>>>(rows);                                   // 0
    build_kernel<<<256, 256>>>(rows, cols, vals);                         // 1
    transpose_kernel<<<dim3(Nd / 32, Bd / 32), dim3(32, 8)>>>(x);         // 2
    spmv_kernel<<<Nd / 8, 256>>>(bc, flag);                               // 3
    gemm_f16_kernel<<<128, 256, GEMM_SMEM>>>((__half*)pa0, W1, b1, bc, flag, ph1, 0);   // 4
    gemm_f16_kernel<<<128, 256, GEMM_SMEM>>>((__half*)ph1, W2, b2, bc, flag, ph2, 0);   // 5
    gemm_f16_kernel<<<128, 256, GEMM_SMEM>>>((__half*)ph2, W3, b3, bc, flag, d_out, 1); // 6
}

// round 7
// speedup vs baseline: 1.5527x; 1.0817x over previous
#include <cuda_runtime.h>
#include <cuda_fp16.h>
#include <cstdint>
#include <math.h>

static constexpr int Nd   = 8192;
static constexpr int Bd   = 256;
static constexpr int NNZc = 16 * Nd;
static constexpr int SLOTS = 64;          // padded CSR row capacity (max ~38 expected)

// ---------------- device scratch (no allocation) ----------------
__device__ __align__(1024) float  g_xt[Nd * Bd];        // x^T [N,B] fp32
__device__ __align__(1024) __half g_a0h[Bd * Nd];       // activations fp16 [B,N]
__device__ __align__(1024) __half g_h1h[Bd * Nd];
__device__ __align__(1024) __half g_h2h[Bd * Nd];
__device__ int   g_cnt[Nd];
__device__ __align__(1024) int2 g_cv[Nd * SLOTS];       // padded {col, val-bits}

// ---------------- helpers ----------------
__device__ __forceinline__ uint32_t smem_to_u32(const void* p) {
    uint32_t a;
    asm("{ .reg .u64 t; cvta.to.shared.u64 t, %1; cvt.u32.u64 %0, t; }" : "=r"(a) : "l"(p));
    return a;
}

__device__ __forceinline__ float selu_f(float x) {
    const float kS = 1.0507009873554805f;
    const float kA = 1.6732632423543772f;
    return x > 0.f ? kS * x : kS * kA * expm1f(x);
}

// SW128 swizzles. A tile: 128 rows x 64 halves = 128B rows.
__device__ __forceinline__ uint32_t swzA64(uint32_t r, uint32_t c) {
    uint32_t byte = r * 128u + c * 2u;
    return byte ^ ((byte >> 3) & 0x70u);
}
// B tile: 128 rows x 64 fp32 = 256B rows.
__device__ __forceinline__ uint32_t swzB64(uint32_t r, uint32_t cw) {
    uint32_t byte = r * 256u + cw * 4u;
    return byte ^ ((byte >> 3) & 0x70u);
}

#define CP_ASYNC16(dst, src) \
    asm volatile("cp.async.cg.shared.global [%0], [%1], 16;" :: "r"(dst), "l"(src) : "memory")
#define CP_COMMIT() asm volatile("cp.async.commit_group;" ::: "memory")
#define CP_WAIT2()  asm volatile("cp.async.wait_group 2;" ::: "memory")

#define LDMATRIX_X4(r0, r1, r2, r3, addr) \
    asm volatile("ldmatrix.sync.aligned.m8n8.x4.shared.b16 {%0,%1,%2,%3}, [%4];" \
        : "=r"(r0), "=r"(r1), "=r"(r2), "=r"(r3) : "r"(addr))

#define MMA16816(d, a, b0, b1) \
    asm volatile("mma.sync.aligned.m16n8k16.row.col.f32.f16.f16.f32 " \
        "{%0,%1,%2,%3}, {%4,%5,%6,%7}, {%8,%9}, {%0,%1,%2,%3};" \
        : "+f"((d)[0]), "+f"((d)[1]), "+f"((d)[2]), "+f"((d)[3]) \
        : "r"((a)[0]), "r"((a)[1]), "r"((a)[2]), "r"((a)[3]), "r"(b0), "r"(b1))

// ---------------- sparse pipeline (3 launches) ----------------
// launch 0: transpose (2048 CTAs) + cnt zero (CTA 2048)
__global__ void __launch_bounds__(256, 2) fused_prep_kernel(const float* __restrict__ x) {
    if (blockIdx.x < 2048) {
        __shared__ float t[32][33];
        int nb = (blockIdx.x & 255) * 32, bb = (blockIdx.x >> 8) * 32;
        int tx = threadIdx.x & 31, ty = threadIdx.x >> 5;
#pragma unroll
        for (int i = 0; i < 32; i += 8)
            t[ty + i][tx] = x[(size_t)(bb + ty + i) * Nd + nb + tx];
        __syncthreads();
#pragma unroll
        for (int i = 0; i < 32; i += 8)
            g_xt[(size_t)(nb + ty + i) * Bd + bb + tx] = t[tx][ty + i];
    } else {
#pragma unroll
        for (int i = 0; i < Nd / 256; i++) g_cnt[threadIdx.x + i * 256] = 0;
    }
}

// launch 1: padded CSR build
__global__ void build_kernel(const int* __restrict__ rows, const int* __restrict__ cols,
                             const float* __restrict__ vals) {
    for (int i = blockIdx.x * blockDim.x + threadIdx.x; i < NNZc; i += gridDim.x * blockDim.x) {
        int r = rows[i];
        int p = atomicAdd(&g_cnt[r], 1);
        g_cv[r * SLOTS + p] = make_int2(cols[i], __float_as_int(vals[i]));
    }
}

// launch 2: warp-per-row SpMV with fused bc/flag fix, fp16 [B,N] output
__global__ void spmv_kernel(const float* __restrict__ bc, const float* __restrict__ flag) {
    int row = blockIdx.x * 8 + (threadIdx.x >> 5);
    int lane = threadIdx.x & 31;
    int n = g_cnt[row];
    const int2* cv = g_cv + row * SLOTS;
    float a0 = 0.f, a1 = 0.f, a2 = 0.f, a3 = 0.f, a4 = 0.f, a5 = 0.f, a6 = 0.f, a7 = 0.f;
    const float* xb = g_xt + lane * 8;
    if (n > 0) {
        int2 c0 = cv[0];
        for (int j = 0; j < n; j++) {
            int2 c1 = (j + 1 < n) ? cv[j + 1] : c0;   // prefetch next
            float v = __int_as_float(c0.y);
            const float4* p = (const float4*)(xb + (size_t)c0.x * Bd);
            float4 u = p[0], w = p[1];
            a0 += v * u.x; a1 += v * u.y; a2 += v * u.z; a3 += v * u.w;
            a4 += v * w.x; a5 += v * w.y; a6 += v * w.z; a7 += v * w.w;
            c0 = c1;
        }
    }
    float bcv = bc[row], fl = flag[row];
    float r[8] = {a0, a1, a2, a3, a4, a5, a6, a7};
#pragma unroll
    for (int i = 0; i < 8; i++)
        g_a0h[(size_t)(lane * 8 + i) * Nd + row] = __float2half_rn(bcv + r[i] * fl);
}

// ---------------- fp16 mma.sync GEMM, k-tile 64, fp32 W converted in-register ----------------
static constexpr int NSTAGE      = 4;
static constexpr int A_BYTES     = 16384;   // 128x64 halves
static constexpr int B_BYTES     = 32768;   // 128x64 fp32
static constexpr int STAGE_BYTES = A_BYTES + B_BYTES;           // 48 KB
static constexpr int GEMM_SMEM   = NSTAGE * STAGE_BYTES;        // 192 KB
static constexpr int KTILES      = Nd / 64; // 128

__device__ __forceinline__ void issue_stage(uint32_t sbase, int buf,
                                            const __half* At, const float* Wt,
                                            int k0, int tid) {
    uint32_t st = sbase + buf * STAGE_BYTES;
    // A: 1024 x 16B chunks (128B/row = 8 chunks)
#pragma unroll
    for (int i = 0; i < 4; i++) {
        int id = tid + i * 256;
        int r = id >> 3, ch = id & 7;
        const __half* src = At + (size_t)r * Nd + k0 + ch * 8;
        CP_ASYNC16(st + swzA64(r, ch * 8), src);
    }
    // B: 2048 x 16B chunks (256B/row = 16 chunks)
#pragma unroll
    for (int i = 0; i < 8; i++) {
        int id = tid + i * 256;
        int r = id >> 4, ch = id & 15;
        const float* src = Wt + (size_t)r * Nd + k0 + ch * 4;
        CP_ASYNC16(st + A_BYTES + swzB64(r, ch * 4), src);
    }
}

struct Frags {
    uint32_t ar[4][4];
    uint32_t b0r[4], b1r[4];
};

__device__ __forceinline__ void load_frags(Frags& f, const char* smem,
                                           int stage, int ks, int wm, int wn, int lane) {
    uint32_t aOff = stage * STAGE_BYTES;
    uint32_t bOff = aOff + A_BYTES;
    uint32_t sb0 = smem_to_u32(smem);
    uint32_t acol = ks * 16 + (lane >> 4) * 8;
#pragma unroll
    for (int mf = 0; mf < 4; mf++) {
        uint32_t row = wm * 64 + mf * 16 + (lane & 15);
        LDMATRIX_X4(f.ar[mf][0], f.ar[mf][1], f.ar[mf][2], f.ar[mf][3],
                    sb0 + aOff + swzA64(row, acol));
    }
    uint32_t nrow = wn * 32 + (lane >> 2);
    uint32_t clo = ks * 16 + (lane & 3) * 2;
#pragma unroll
    for (int nf = 0; nf < 4; nf++) {
        uint32_t r = nrow + nf * 8;
        float2 lo = *(const float2*)(smem + bOff + swzB64(r, clo));
        float2 hi = *(const float2*)(smem + bOff + swzB64(r, clo + 8));
        __half2 h0 = __floats2half2_rn(lo.x, lo.y);
        __half2 h1 = __floats2half2_rn(hi.x, hi.y);
        f.b0r[nf] = *(uint32_t*)&h0;
        f.b1r[nf] = *(uint32_t*)&h1;
    }
}

__global__ void __launch_bounds__(256, 1)
gemm_f16_kernel(const __half* __restrict__ Ag, const float* __restrict__ Wg,
                const float* __restrict__ bias,
                const float* __restrict__ bc, const float* __restrict__ flag,
                void* __restrict__ outv, int mode)   // 0=selu->half, 1=addcmul->float
{
    extern __shared__ char smem[];
    uint32_t sb = smem_to_u32(smem);
    int tid = threadIdx.x, lane = tid & 31, w = tid >> 5;
    int wm = w & 1, wn = w >> 1;
    int mtile = blockIdx.x & 1, ntile = blockIdx.x >> 1;

    const __half* At = Ag + (size_t)(mtile * 128) * Nd;
    const float*  Wt = Wg + (size_t)(ntile * 128) * Nd;

    float acc[4][4][4];
#pragma unroll
    for (int a = 0; a < 4; a++)
#pragma unroll
        for (int b = 0; b < 4; b++)
#pragma unroll
            for (int c = 0; c < 4; c++) acc[a][b][c] = 0.f;

#pragma unroll
    for (int s = 0; s < NSTAGE - 1; s++) {          // stages 0,1,2
        issue_stage(sb, s, At, Wt, s * 64, tid);
        CP_COMMIT();
    }

    Frags f0, f1;
#pragma unroll 1
    for (int t = 0; t < KTILES; t++) {
        // committed groups so far: 3 + t; wait 2 -> stages 0..t complete
        CP_WAIT2();
        __syncthreads();     // visibility of stage t; stage t-1 reads all done
        if (t + 3 < KTILES)
            issue_stage(sb, (t + 3) % NSTAGE, At, Wt, (t + 3) * 64, tid);
        CP_COMMIT();         // unconditional: exact group accounting

        int st = t % NSTAGE;
        load_frags(f0, smem, st, 0, wm, wn, lane);
#pragma unroll
        for (int ks = 0; ks < 4; ks++) {
            Frags& cur = (ks & 1) ? f1 : f0;
            Frags& nxt = (ks & 1) ? f0 : f1;
            if (ks < 3) load_frags(nxt, smem, st, ks + 1, wm, wn, lane);
#pragma unroll
            for (int mf = 0; mf < 4; mf++)
#pragma unroll
                for (int nf = 0; nf < 4; nf++)
                    MMA16816(acc[mf][nf], cur.ar[mf], cur.b0r[nf], cur.b1r[nf]);
        }
    }

#pragma unroll
    for (int mf = 0; mf < 4; mf++) {
#pragma unroll
        for (int nf = 0; nf < 4; nf++) {
            int r0 = mtile * 128 + wm * 64 + mf * 16 + (lane >> 2);
            int c0 = ntile * 128 + wn * 32 + nf * 8 + (lane & 3) * 2;
            float b0 = __ldg(&bias[c0]), b1 = __ldg(&bias[c0 + 1]);
            float v00 = acc[mf][nf][0] + b0, v01 = acc[mf][nf][1] + b1;
            float v10 = acc[mf][nf][2] + b0, v11 = acc[mf][nf][3] + b1;
            if (mode == 0) {
                __half2* o0 = (__half2*)((__half*)outv + (size_t)r0 * Nd + c0);
                __half2* o1 = (__half2*)((__half*)outv + (size_t)(r0 + 8) * Nd + c0);
                *o0 = __floats2half2_rn(selu_f(v00), selu_f(v01));
                *o1 = __floats2half2_rn(selu_f(v10), selu_f(v11));
            } else {
                float bc0 = __ldg(&bc[c0]), bc1 = __ldg(&bc[c0 + 1]);
                float fl0 = __ldg(&flag[c0]), fl1 = __ldg(&flag[c0 + 1]);
                float* o0 = (float*)outv + (size_t)r0 * Nd + c0;
                float* o1 = (float*)outv + (size_t)(r0 + 8) * Nd + c0;
                o0[0] = bc0 + v00 * fl0; o0[1] = bc1 + v01 * fl1;
                o1[0] = bc0 + v10 * fl0; o1[1] = bc1 + v11 * fl1;
            }
        }
    }
}

// ---------------- host ----------------
extern "C" void kernel_launch(void* const* d_in, const int* in_sizes, int n_in,
                              void* d_out, int out_size) {
    const float* x    = (const float*)d_in[0];
    const float* vals = (const float*)d_in[1];
    const float* bc   = (const float*)d_in[2];
    const float* flag = (const float*)d_in[3];
    const float* W1   = (const float*)d_in[4];
    const float* b1   = (const float*)d_in[5];
    const float* W2   = (const float*)d_in[6];
    const float* b2   = (const float*)d_in[7];
    const float* W3   = (const float*)d_in[8];
    const float* b3   = (const float*)d_in[9];
    const int*   rows = (const int*)d_in[10];
    const int*   cols = (const int*)d_in[11];

    void *pa0, *ph1, *ph2;
    cudaGetSymbolAddress(&pa0, g_a0h);
    cudaGetSymbolAddress(&ph1, g_h1h);
    cudaGetSymbolAddress(&ph2, g_h2h);

    cudaFuncSetAttribute(gemm_f16_kernel, cudaFuncAttributeMaxDynamicSharedMemorySize, GEMM_SMEM);

    fused_prep_kernel<<<2049, 256>>>(x);                                  // 0
    build_kernel<<<256, 256>>>(rows, cols, vals);                         // 1
    spmv_kernel<<<Nd / 8, 256>>>(bc, flag);                               // 2
    gemm_f16_kernel<<<128, 256, GEMM_SMEM>>>((__half*)pa0, W1, b1, bc, flag, ph1, 0);   // 3 <- ncu
    gemm_f16_kernel<<<128, 256, GEMM_SMEM>>>((__half*)ph1, W2, b2, bc, flag, ph2, 0);   // 4
    gemm_f16_kernel<<<128, 256, GEMM_SMEM>>>((__half*)ph2, W3, b3, bc, flag, d_out, 1); // 5
}